// round 1
// baseline (speedup 1.0000x reference)
#include <cuda_runtime.h>
#include <math.h>

// Problem constants (from reference):
//   features: (1, 50, 50, 1024) fp32  NHWC
//   boxes:    (1, 300, 4) fp32  [y1, x1, y2, x2], sorted so y1<=y2, x1<=x2
//   CROP=14 bilinear crop, then 2x2 max pool -> out (1, 300, 7, 7, 1024) fp32

#define FH 50
#define FW 50
#define FC 1024
#define NBOX 300
#define CROP 14
#define PO 7          // pooled output size per axis
#define C4 (FC / 4)   // 256 float4 channel groups

__global__ __launch_bounds__(C4, 8)
void roi_pool_kernel(const float* __restrict__ feat,
                     const float* __restrict__ boxes,
                     float* __restrict__ out)
{
    const int blk = blockIdx.x;          // 0 .. NBOX*PO*PO-1
    const int n   = blk / (PO * PO);     // box index
    const int p   = blk - n * (PO * PO); // pooled pixel index (py*7+px)
    const int py  = p / PO;
    const int px  = p - py * PO;
    const int c4  = threadIdx.x;         // float4 channel group 0..255

    // Box coords (broadcast load; all threads same address -> L1 broadcast)
    const float by1 = boxes[n * 4 + 0];
    const float bx1 = boxes[n * 4 + 1];
    const float by2 = boxes[n * 4 + 2];
    const float bx2 = boxes[n * 4 + 3];

    const float scale = 1.0f / (float)(CROP - 1);
    const float dy = (by2 - by1) * (float)(FH - 1) * scale;
    const float dx = (bx2 - bx1) * (float)(FW - 1) * scale;
    const float ybase = by1 * (float)(FH - 1);
    const float xbase = bx1 * (float)(FW - 1);

    // Per-sample (2 along each axis for the 2x2 pool window) bilinear coords.
    int y0[2], y1i[2], x0[2], x1i[2];
    float wy[2], wx[2];
#pragma unroll
    for (int s = 0; s < 2; s++) {
        const float ys = ybase + (float)(2 * py + s) * dy;
        const float yf = floorf(ys);
        wy[s] = ys - yf;                       // reference uses unclipped floor
        int yy = (int)yf;
        yy = min(max(yy, 0), FH - 1);
        y0[s]  = yy;
        y1i[s] = min(yy + 1, FH - 1);

        const float xs = xbase + (float)(2 * px + s) * dx;
        const float xf = floorf(xs);
        wx[s] = xs - xf;
        int xx = (int)xf;
        xx = min(max(xx, 0), FW - 1);
        x0[s]  = xx;
        x1i[s] = min(xx + 1, FW - 1);
    }

    const float4* __restrict__ f4 = (const float4*)feat;

    float4 m;
    m.x = -INFINITY; m.y = -INFINITY; m.z = -INFINITY; m.w = -INFINITY;

#pragma unroll
    for (int sy = 0; sy < 2; sy++) {
#pragma unroll
        for (int sx = 0; sx < 2; sx++) {
            const int rt = y0[sy]  * FW;
            const int rb = y1i[sy] * FW;
            const float4 tl = f4[(rt + x0[sx])  * C4 + c4];
            const float4 tr = f4[(rt + x1i[sx]) * C4 + c4];
            const float4 bl = f4[(rb + x0[sx])  * C4 + c4];
            const float4 br = f4[(rb + x1i[sx]) * C4 + c4];

            const float a = wx[sx];
            const float b = wy[sy];

            // Match reference: top = tl + (tr-tl)*wx; bot = bl + (br-bl)*wx;
            //                  v = top + (bot-top)*wy
            float4 v;
            {
                const float tx = tl.x + (tr.x - tl.x) * a;
                const float bx = bl.x + (br.x - bl.x) * a;
                v.x = tx + (bx - tx) * b;
            }
            {
                const float ty = tl.y + (tr.y - tl.y) * a;
                const float by = bl.y + (br.y - bl.y) * a;
                v.y = ty + (by - ty) * b;
            }
            {
                const float tz = tl.z + (tr.z - tl.z) * a;
                const float bz = bl.z + (br.z - bl.z) * a;
                v.z = tz + (bz - tz) * b;
            }
            {
                const float tw = tl.w + (tr.w - tl.w) * a;
                const float bw = bl.w + (br.w - bl.w) * a;
                v.w = tw + (bw - tw) * b;
            }

            m.x = fmaxf(m.x, v.x);
            m.y = fmaxf(m.y, v.y);
            m.z = fmaxf(m.z, v.z);
            m.w = fmaxf(m.w, v.w);
        }
    }

    // Output: (1, 300, 7, 7, 1024) contiguous; blk covers (n, py, px).
    float4* __restrict__ o4 = (float4*)out;
    o4[blk * C4 + c4] = m;
}

extern "C" void kernel_launch(void* const* d_in, const int* in_sizes, int n_in,
                              void* d_out, int out_size)
{
    const float* feat  = (const float*)d_in[0];   // 50*50*1024 floats
    const float* boxes = (const float*)d_in[1];   // 300*4 floats
    float* out = (float*)d_out;                   // 300*7*7*1024 floats

    const int grid = NBOX * PO * PO;              // 14700 blocks
    roi_pool_kernel<<<grid, C4>>>(feat, boxes, out);
}

// round 2
// speedup vs baseline: 1.0508x; 1.0508x over previous
#include <cuda_runtime.h>
#include <math.h>

// features: (1, 50, 50, 1024) fp32 NHWC ; boxes: (1, 300, 4) fp32 [y1,x1,y2,x2]
// crop 14x14 bilinear, 2x2 max pool -> out (1, 300, 7, 7, 1024) fp32

#define FH 50
#define FW 50
#define FC 1024
#define NBOX 300
#define CROP 14
#define PO 7
#define C4 (FC / 4)

__device__ __forceinline__ float4 bilin(const float4 tl, const float4 tr,
                                        const float4 bl, const float4 br,
                                        const float a, const float b)
{
    float4 v;
    {
        const float t = tl.x + (tr.x - tl.x) * a;
        const float u = bl.x + (br.x - bl.x) * a;
        v.x = t + (u - t) * b;
    }
    {
        const float t = tl.y + (tr.y - tl.y) * a;
        const float u = bl.y + (br.y - bl.y) * a;
        v.y = t + (u - t) * b;
    }
    {
        const float t = tl.z + (tr.z - tl.z) * a;
        const float u = bl.z + (br.z - bl.z) * a;
        v.z = t + (u - t) * b;
    }
    {
        const float t = tl.w + (tr.w - tl.w) * a;
        const float u = bl.w + (br.w - bl.w) * a;
        v.w = t + (u - t) * b;
    }
    return v;
}

// YC/XC: 0 = sample1 rows identical to sample0 (2 distinct),
//        1 = sample1 top row == sample0 bottom row (3 distinct, chain),
//        2 = disjoint (4 distinct).
// Distinct row list: {r0, r1, (YC==1 ? r3 : r2), r3}; sample0 uses (0,1),
// sample1 uses (YC, YC+1). Same scheme for columns.
template <int YC, int XC>
__device__ __forceinline__ float4 sample_max(
    const float4* __restrict__ f4, const int c4,
    const int r0, const int r1, const int r2, const int r3,
    const int c0, const int c1, const int c2, const int c3,
    const float wy0, const float wy1, const float wx0, const float wx1)
{
    constexpr int NR = YC + 2;
    constexpr int NC = XC + 2;

    const int rr[4] = {r0, r1, (YC == 1 ? r3 : r2), r3};
    const int cc[4] = {c0, c1, (XC == 1 ? c3 : c2), c3};

    float4 g[NR][NC];
#pragma unroll
    for (int i = 0; i < NR; i++) {
        const int rb = rr[i] * FW;
#pragma unroll
        for (int j = 0; j < NC; j++) {
            g[i][j] = f4[(rb + cc[j]) * C4 + c4];
        }
    }

    float4 m;
    m.x = -INFINITY; m.y = -INFINITY; m.z = -INFINITY; m.w = -INFINITY;

#pragma unroll
    for (int sy = 0; sy < 2; sy++) {
        constexpr int dummy = 0; (void)dummy;
        const int rt = sy ? YC : 0;
        const float b = sy ? wy1 : wy0;
#pragma unroll
        for (int sx = 0; sx < 2; sx++) {
            const int cl = sx ? XC : 0;
            const float a = sx ? wx1 : wx0;
            const float4 v = bilin(g[rt][cl], g[rt][cl + 1],
                                   g[rt + 1][cl], g[rt + 1][cl + 1], a, b);
            m.x = fmaxf(m.x, v.x);
            m.y = fmaxf(m.y, v.y);
            m.z = fmaxf(m.z, v.z);
            m.w = fmaxf(m.w, v.w);
        }
    }
    return m;
}

__global__ __launch_bounds__(C4)
void roi_pool_kernel(const float* __restrict__ feat,
                     const float* __restrict__ boxes,
                     float* __restrict__ out)
{
    const int blk = blockIdx.x;
    const int n   = blk / (PO * PO);
    const int p   = blk - n * (PO * PO);
    const int py  = p / PO;
    const int px  = p - py * PO;
    const int c4  = threadIdx.x;

    const float by1 = boxes[n * 4 + 0];
    const float bx1 = boxes[n * 4 + 1];
    const float by2 = boxes[n * 4 + 2];
    const float bx2 = boxes[n * 4 + 3];

    const float scale = 1.0f / (float)(CROP - 1);
    const float dy = (by2 - by1) * (float)(FH - 1) * scale;
    const float dx = (bx2 - bx1) * (float)(FW - 1) * scale;
    const float ybase = by1 * (float)(FH - 1);
    const float xbase = bx1 * (float)(FW - 1);

    // Two bilinear samples per axis (2x2 pool window over 14x14 crop grid).
    int r0, r1, r2, r3, c0, c1, c2, c3;
    float wy0, wy1, wx0, wx1;
    {
        const float ys0 = ybase + (float)(2 * py) * dy;
        const float yf0 = floorf(ys0);
        wy0 = ys0 - yf0;
        int yy = min(max((int)yf0, 0), FH - 1);
        r0 = yy; r1 = min(yy + 1, FH - 1);

        const float ys1 = ys0 + dy;
        const float yf1 = floorf(ys1);
        wy1 = ys1 - yf1;
        yy = min(max((int)yf1, 0), FH - 1);
        r2 = yy; r3 = min(yy + 1, FH - 1);

        const float xs0 = xbase + (float)(2 * px) * dx;
        const float xf0 = floorf(xs0);
        wx0 = xs0 - xf0;
        int xx = min(max((int)xf0, 0), FW - 1);
        c0 = xx; c1 = min(xx + 1, FW - 1);

        const float xs1 = xs0 + dx;
        const float xf1 = floorf(xs1);
        wx1 = xs1 - xf1;
        xx = min(max((int)xf1, 0), FW - 1);
        c2 = xx; c3 = min(xx + 1, FW - 1);
    }

    // Classify row/col sharing (uniform across the block -> no divergence).
    const int yc = (r2 == r0) ? 0 : ((r2 == r1) ? 1 : 2);
    const int xc = (c2 == c0) ? 0 : ((c2 == c1) ? 1 : 2);

    const float4* __restrict__ f4 = (const float4*)feat;
    float4 m;

    switch (yc * 3 + xc) {
        case 0: m = sample_max<0,0>(f4,c4,r0,r1,r2,r3,c0,c1,c2,c3,wy0,wy1,wx0,wx1); break;
        case 1: m = sample_max<0,1>(f4,c4,r0,r1,r2,r3,c0,c1,c2,c3,wy0,wy1,wx0,wx1); break;
        case 2: m = sample_max<0,2>(f4,c4,r0,r1,r2,r3,c0,c1,c2,c3,wy0,wy1,wx0,wx1); break;
        case 3: m = sample_max<1,0>(f4,c4,r0,r1,r2,r3,c0,c1,c2,c3,wy0,wy1,wx0,wx1); break;
        case 4: m = sample_max<1,1>(f4,c4,r0,r1,r2,r3,c0,c1,c2,c3,wy0,wy1,wx0,wx1); break;
        case 5: m = sample_max<1,2>(f4,c4,r0,r1,r2,r3,c0,c1,c2,c3,wy0,wy1,wx0,wx1); break;
        case 6: m = sample_max<2,0>(f4,c4,r0,r1,r2,r3,c0,c1,c2,c3,wy0,wy1,wx0,wx1); break;
        case 7: m = sample_max<2,1>(f4,c4,r0,r1,r2,r3,c0,c1,c2,c3,wy0,wy1,wx0,wx1); break;
        default:m = sample_max<2,2>(f4,c4,r0,r1,r2,r3,c0,c1,c2,c3,wy0,wy1,wx0,wx1); break;
    }

    float4* __restrict__ o4 = (float4*)out;
    o4[blk * C4 + c4] = m;
}

extern "C" void kernel_launch(void* const* d_in, const int* in_sizes, int n_in,
                              void* d_out, int out_size)
{
    const float* feat  = (const float*)d_in[0];
    const float* boxes = (const float*)d_in[1];
    float* out = (float*)d_out;

    roi_pool_kernel<<<NBOX * PO * PO, C4>>>(feat, boxes, out);
}

// round 3
// speedup vs baseline: 1.2529x; 1.1923x over previous
#include <cuda_runtime.h>
#include <math.h>

// features: (1, 50, 50, 1024) fp32 NHWC ; boxes: (1, 300, 4) fp32 [y1,x1,y2,x2]
// crop 14x14 bilinear, 2x2 max pool -> out (1, 300, 7, 7, 1024) fp32

#define FH 50
#define FW 50
#define FC 1024
#define NBOX 300
#define CROP 14
#define PO 7
#define C4 (FC / 4)      // 256 float4 channel groups
#define TPB 128          // threads per block; each thread does 2 channel groups

__device__ __forceinline__ float4 bilin(const float4 tl, const float4 tr,
                                        const float4 bl, const float4 br,
                                        const float a, const float b)
{
    float4 v;
    {
        const float t = tl.x + (tr.x - tl.x) * a;
        const float u = bl.x + (br.x - bl.x) * a;
        v.x = t + (u - t) * b;
    }
    {
        const float t = tl.y + (tr.y - tl.y) * a;
        const float u = bl.y + (br.y - bl.y) * a;
        v.y = t + (u - t) * b;
    }
    {
        const float t = tl.z + (tr.z - tl.z) * a;
        const float u = bl.z + (br.z - bl.z) * a;
        v.z = t + (u - t) * b;
    }
    {
        const float t = tl.w + (tr.w - tl.w) * a;
        const float u = bl.w + (br.w - bl.w) * a;
        v.w = t + (u - t) * b;
    }
    return v;
}

// YC/XC: 0 = sample1 rows identical to sample0 (2 distinct),
//        1 = sample1 top row == sample0 bottom row (3 distinct, chain),
//        2 = disjoint (4 distinct).
template <int YC, int XC>
__device__ __forceinline__ float4 sample_max(
    const float4* __restrict__ f4, const int base_c4,
    const int r0, const int r1, const int r2, const int r3,
    const int c0, const int c1, const int c2, const int c3,
    const float wy0, const float wy1, const float wx0, const float wx1)
{
    constexpr int NR = YC + 2;
    constexpr int NC = XC + 2;

    const int rr[4] = {r0, r1, (YC == 1 ? r3 : r2), r3};
    const int cc[4] = {c0, c1, (XC == 1 ? c3 : c2), c3};

    // Precompute element offsets once (shared by both channel groups).
    int off[NR][NC];
#pragma unroll
    for (int i = 0; i < NR; i++) {
        const int rb = rr[i] * FW;
#pragma unroll
        for (int j = 0; j < NC; j++) {
            off[i][j] = (rb + cc[j]) * C4 + base_c4;
        }
    }

    float4 g[NR][NC];
#pragma unroll
    for (int i = 0; i < NR; i++) {
#pragma unroll
        for (int j = 0; j < NC; j++) {
            g[i][j] = f4[off[i][j]];
        }
    }

    float4 m;
    m.x = -INFINITY; m.y = -INFINITY; m.z = -INFINITY; m.w = -INFINITY;

#pragma unroll
    for (int sy = 0; sy < 2; sy++) {
        const int rt = sy ? YC : 0;
        const float b = sy ? wy1 : wy0;
#pragma unroll
        for (int sx = 0; sx < 2; sx++) {
            const int cl = sx ? XC : 0;
            const float a = sx ? wx1 : wx0;
            const float4 v = bilin(g[rt][cl], g[rt][cl + 1],
                                   g[rt + 1][cl], g[rt + 1][cl + 1], a, b);
            m.x = fmaxf(m.x, v.x);
            m.y = fmaxf(m.y, v.y);
            m.z = fmaxf(m.z, v.z);
            m.w = fmaxf(m.w, v.w);
        }
    }
    return m;
}

template <int YC, int XC>
__device__ __forceinline__ void do_case(
    const float4* __restrict__ f4, float4* __restrict__ o4,
    const int blk, const int c4,
    const int r0, const int r1, const int r2, const int r3,
    const int c0, const int c1, const int c2, const int c3,
    const float wy0, const float wy1, const float wx0, const float wx1)
{
    // Two channel groups per thread; identical addressing +/- constant offset.
#pragma unroll
    for (int cg = 0; cg < 2; cg++) {
        const int ch = c4 + cg * TPB;
        const float4 m = sample_max<YC, XC>(f4, ch, r0, r1, r2, r3,
                                            c0, c1, c2, c3, wy0, wy1, wx0, wx1);
        o4[blk * C4 + ch] = m;
    }
}

__global__ __launch_bounds__(TPB, 6)
void roi_pool_kernel(const float* __restrict__ feat,
                     const float* __restrict__ boxes,
                     float* __restrict__ out)
{
    const int blk = blockIdx.x;
    const int n   = blk / (PO * PO);
    const int p   = blk - n * (PO * PO);
    const int py  = p / PO;
    const int px  = p - py * PO;
    const int c4  = threadIdx.x;

    const float by1 = boxes[n * 4 + 0];
    const float bx1 = boxes[n * 4 + 1];
    const float by2 = boxes[n * 4 + 2];
    const float bx2 = boxes[n * 4 + 3];

    const float scale = 1.0f / (float)(CROP - 1);
    const float dy = (by2 - by1) * (float)(FH - 1) * scale;
    const float dx = (bx2 - bx1) * (float)(FW - 1) * scale;
    const float ybase = by1 * (float)(FH - 1);
    const float xbase = bx1 * (float)(FW - 1);

    int r0, r1, r2, r3, c0, c1, c2, c3;
    float wy0, wy1, wx0, wx1;
    {
        const float ys0 = ybase + (float)(2 * py) * dy;
        const float yf0 = floorf(ys0);
        wy0 = ys0 - yf0;
        int yy = min(max((int)yf0, 0), FH - 1);
        r0 = yy; r1 = min(yy + 1, FH - 1);

        const float ys1 = ys0 + dy;
        const float yf1 = floorf(ys1);
        wy1 = ys1 - yf1;
        yy = min(max((int)yf1, 0), FH - 1);
        r2 = yy; r3 = min(yy + 1, FH - 1);

        const float xs0 = xbase + (float)(2 * px) * dx;
        const float xf0 = floorf(xs0);
        wx0 = xs0 - xf0;
        int xx = min(max((int)xf0, 0), FW - 1);
        c0 = xx; c1 = min(xx + 1, FW - 1);

        const float xs1 = xs0 + dx;
        const float xf1 = floorf(xs1);
        wx1 = xs1 - xf1;
        xx = min(max((int)xf1, 0), FW - 1);
        c2 = xx; c3 = min(xx + 1, FW - 1);
    }

    // Block-uniform classification -> no divergence.
    const int yc = (r2 == r0) ? 0 : ((r2 == r1) ? 1 : 2);
    const int xc = (c2 == c0) ? 0 : ((c2 == c1) ? 1 : 2);

    const float4* __restrict__ f4 = (const float4*)feat;
    float4* __restrict__ o4 = (float4*)out;

    switch (yc * 3 + xc) {
        case 0: do_case<0,0>(f4,o4,blk,c4,r0,r1,r2,r3,c0,c1,c2,c3,wy0,wy1,wx0,wx1); break;
        case 1: do_case<0,1>(f4,o4,blk,c4,r0,r1,r2,r3,c0,c1,c2,c3,wy0,wy1,wx0,wx1); break;
        case 2: do_case<0,2>(f4,o4,blk,c4,r0,r1,r2,r3,c0,c1,c2,c3,wy0,wy1,wx0,wx1); break;
        case 3: do_case<1,0>(f4,o4,blk,c4,r0,r1,r2,r3,c0,c1,c2,c3,wy0,wy1,wx0,wx1); break;
        case 4: do_case<1,1>(f4,o4,blk,c4,r0,r1,r2,r3,c0,c1,c2,c3,wy0,wy1,wx0,wx1); break;
        case 5: do_case<1,2>(f4,o4,blk,c4,r0,r1,r2,r3,c0,c1,c2,c3,wy0,wy1,wx0,wx1); break;
        case 6: do_case<2,0>(f4,o4,blk,c4,r0,r1,r2,r3,c0,c1,c2,c3,wy0,wy1,wx0,wx1); break;
        case 7: do_case<2,1>(f4,o4,blk,c4,r0,r1,r2,r3,c0,c1,c2,c3,wy0,wy1,wx0,wx1); break;
        default:do_case<2,2>(f4,o4,blk,c4,r0,r1,r2,r3,c0,c1,c2,c3,wy0,wy1,wx0,wx1); break;
    }
}

extern "C" void kernel_launch(void* const* d_in, const int* in_sizes, int n_in,
                              void* d_out, int out_size)
{
    const float* feat  = (const float*)d_in[0];
    const float* boxes = (const float*)d_in[1];
    float* out = (float*)d_out;

    roi_pool_kernel<<<NBOX * PO * PO, TPB>>>(feat, boxes, out);
}